// round 2
// baseline (speedup 1.0000x reference)
#include <cuda_runtime.h>

#define HID   1024
#define NH    16
#define DK    64
#define BATCH 4
#define SEQ   2048
#define MTOT  (BATCH*SEQ)

// Scratch (allocation-free rule: __device__ globals)
__device__ float g_q[(size_t)BATCH*NH*SEQ*DK];   // [b,h,s,d], pre-scaled by 1/sqrt(dk)
__device__ float g_k[(size_t)BATCH*NH*SEQ*DK];
__device__ float g_v[(size_t)BATCH*NH*SEQ*DK];
__device__ float g_ctx[(size_t)MTOT*HID];        // [b,s,h*dk] for output projection

// ---------------------------------------------------------------------------
// Tiled SGEMM: Y[m][n] = sum_k X[m][k] * W[n][k] + bias[n]
// BM=BN=128, BK=16, 256 threads, 8x8 per-thread tile (4+4 split layout).
// MODE 0: QKV projection (blockIdx.z selects matrix, scatter-store to g_q/g_k/g_v)
// MODE 1: output projection (X = g_ctx, plain store to OutPlain)
// ---------------------------------------------------------------------------
template<int MODE>
__global__ __launch_bounds__(256, 2)
void gemm_kernel(const float* __restrict__ Xin,
                 const float* __restrict__ W0, const float* __restrict__ B0,
                 const float* __restrict__ W1, const float* __restrict__ B1,
                 const float* __restrict__ W2, const float* __restrict__ B2,
                 float* __restrict__ OutPlain)
{
    const float* X = (MODE == 1) ? g_ctx : Xin;
    const int z = blockIdx.z;
    const float* W;
    const float* bias;
    if (MODE == 0) {
        W    = (z == 0) ? W0 : ((z == 1) ? W1 : W2);
        bias = (z == 0) ? B0 : ((z == 1) ? B1 : B2);
    } else {
        W = W0; bias = B0;
    }

    __shared__ float As[16][128];
    __shared__ float Bs[16][128];

    const int m0  = blockIdx.x * 128;
    const int n0  = blockIdx.y * 128;
    const int tid = threadIdx.x;
    const int tr  = tid >> 4;   // 0..15
    const int tc  = tid & 15;   // 0..15

    float acc[8][8];
#pragma unroll
    for (int i = 0; i < 8; i++)
#pragma unroll
        for (int j = 0; j < 8; j++) acc[i][j] = 0.f;

    const float* Ap = X + (size_t)m0 * HID;
    const float* Bp = W + (size_t)n0 * HID;

    for (int k0 = 0; k0 < HID; k0 += 16) {
#pragma unroll
        for (int u = 0; u < 2; u++) {
            int f   = tid + u * 256;          // 0..511 float4 slots (128 rows x 4 f4)
            int row = f >> 2;
            int c4  = (f & 3) << 2;
            float4 a = *(const float4*)(Ap + (size_t)row * HID + k0 + c4);
            As[c4 + 0][row] = a.x; As[c4 + 1][row] = a.y;
            As[c4 + 2][row] = a.z; As[c4 + 3][row] = a.w;
            float4 b = *(const float4*)(Bp + (size_t)row * HID + k0 + c4);
            Bs[c4 + 0][row] = b.x; Bs[c4 + 1][row] = b.y;
            Bs[c4 + 2][row] = b.z; Bs[c4 + 3][row] = b.w;
        }
        __syncthreads();

#pragma unroll
        for (int kk = 0; kk < 16; kk++) {
            float ra[8], rb[8];
            *(float4*)&ra[0] = *(const float4*)&As[kk][(tr << 2)];
            *(float4*)&ra[4] = *(const float4*)&As[kk][64 + (tr << 2)];
            *(float4*)&rb[0] = *(const float4*)&Bs[kk][(tc << 2)];
            *(float4*)&rb[4] = *(const float4*)&Bs[kk][64 + (tc << 2)];
#pragma unroll
            for (int i = 0; i < 8; i++)
#pragma unroll
                for (int j = 0; j < 8; j++)
                    acc[i][j] = fmaf(ra[i], rb[j], acc[i][j]);
        }
        __syncthreads();
    }

#pragma unroll
    for (int i = 0; i < 8; i++) {
        int m = m0 + ((i >> 2) << 6) + (tr << 2) + (i & 3);
#pragma unroll
        for (int j = 0; j < 8; j++) {
            int n = n0 + ((j >> 2) << 6) + (tc << 2) + (j & 3);
            float val = acc[i][j] + bias[n];
            if (MODE == 0) {
                float* dst = (z == 0) ? g_q : ((z == 1) ? g_k : g_v);
                if (z == 0) val *= 0.125f;   // 1/sqrt(64)
                int bb = m >> 11, s = m & 2047, hh = n >> 6, d = n & 63;
                dst[(((size_t)(bb * NH + hh)) * SEQ + s) * DK + d] = val;
            } else {
                OutPlain[(size_t)m * HID + n] = val;
            }
        }
    }
}

// ---------------------------------------------------------------------------
// Flash attention: one thread per query row. K/V streamed through smem in
// 32-key chunks; per-thread score staging in padded smem row (bank-conflict-
// free); online softmax with chunk-max.
// ---------------------------------------------------------------------------
__global__ __launch_bounds__(128, 2)
void attn_kernel()
{
    const int b   = blockIdx.z;
    const int h   = blockIdx.y;
    const int tid = threadIdx.x;
    const int qi  = blockIdx.x * 128 + tid;

    const size_t bh = (size_t)(b * NH + h);
    const float* qp = g_q + (bh * SEQ + qi) * DK;
    const float* kb = g_k + bh * SEQ * DK;
    const float* vb = g_v + bh * SEQ * DK;

    __shared__ float Ks[32][64];
    __shared__ float Vs[32][64];
    __shared__ float Ss[128][33];   // padded: conflict-free per-thread rows

    float4 qv[16];
#pragma unroll
    for (int d4 = 0; d4 < 16; d4++) qv[d4] = *(const float4*)(qp + d4 * 4);

    float4 acc[16];
#pragma unroll
    for (int d4 = 0; d4 < 16; d4++) acc[d4] = make_float4(0.f, 0.f, 0.f, 0.f);
    float mrun = -1e30f, lrun = 0.f;

    for (int kc = 0; kc < SEQ; kc += 32) {
        // cooperative chunk load: 32 rows x 64 floats = 512 float4, contiguous
        const float4* ks = (const float4*)(kb + (size_t)kc * DK);
        const float4* vs = (const float4*)(vb + (size_t)kc * DK);
        float4* kd = (float4*)&Ks[0][0];
        float4* vd = (float4*)&Vs[0][0];
#pragma unroll
        for (int u = 0; u < 4; u++) {
            kd[tid + u * 128] = ks[tid + u * 128];
            vd[tid + u * 128] = vs[tid + u * 128];
        }
        __syncthreads();

        // scores for this chunk + chunk max
        float cmax = -1e30f;
#pragma unroll 4
        for (int j = 0; j < 32; j++) {
            float sum = 0.f;
#pragma unroll
            for (int d4 = 0; d4 < 16; d4++) {
                float4 kv = *(const float4*)&Ks[j][d4 * 4];   // broadcast LDS
                sum = fmaf(qv[d4].x, kv.x, sum);
                sum = fmaf(qv[d4].y, kv.y, sum);
                sum = fmaf(qv[d4].z, kv.z, sum);
                sum = fmaf(qv[d4].w, kv.w, sum);
            }
            Ss[tid][j] = sum;
            cmax = fmaxf(cmax, sum);
        }

        float newm = fmaxf(mrun, cmax);
        float corr = __expf(mrun - newm);   // 0 on first chunk (exp(-inf))
        mrun = newm;
        lrun *= corr;
#pragma unroll
        for (int d4 = 0; d4 < 16; d4++) {
            acc[d4].x *= corr; acc[d4].y *= corr;
            acc[d4].z *= corr; acc[d4].w *= corr;
        }

        // p = exp(s - m); acc += p * V
#pragma unroll 4
        for (int j = 0; j < 32; j++) {
            float p = __expf(Ss[tid][j] - mrun);
            lrun += p;
#pragma unroll
            for (int d4 = 0; d4 < 16; d4++) {
                float4 vv = *(const float4*)&Vs[j][d4 * 4];   // broadcast LDS
                acc[d4].x = fmaf(p, vv.x, acc[d4].x);
                acc[d4].y = fmaf(p, vv.y, acc[d4].y);
                acc[d4].z = fmaf(p, vv.z, acc[d4].z);
                acc[d4].w = fmaf(p, vv.w, acc[d4].w);
            }
        }
        __syncthreads();
    }

    const float inv = 1.f / lrun;
    float* op = g_ctx + ((size_t)(b * SEQ) + qi) * HID + h * DK;
#pragma unroll
    for (int d4 = 0; d4 < 16; d4++) {
        float4 r = acc[d4];
        r.x *= inv; r.y *= inv; r.z *= inv; r.w *= inv;
        *(float4*)(op + d4 * 4) = r;
    }
}

// ---------------------------------------------------------------------------
extern "C" void kernel_launch(void* const* d_in, const int* in_sizes, int n_in,
                              void* d_out, int out_size)
{
    (void)in_sizes; (void)n_in; (void)out_size;
    const float* tgt = (const float*)d_in[0];
    const float* Wq  = (const float*)d_in[1];
    const float* bq  = (const float*)d_in[2];
    const float* Wk  = (const float*)d_in[3];
    const float* bk  = (const float*)d_in[4];
    const float* Wv  = (const float*)d_in[5];
    const float* bv  = (const float*)d_in[6];
    const float* Wo  = (const float*)d_in[7];
    const float* bo  = (const float*)d_in[8];
    float* out = (float*)d_out;

    dim3 gQKV(MTOT / 128, HID / 128, 3);
    gemm_kernel<0><<<gQKV, 256>>>(tgt, Wq, bq, Wk, bk, Wv, bv, nullptr);

    dim3 gATT(SEQ / 128, NH, BATCH);
    attn_kernel<<<gATT, 128>>>();

    dim3 gOUT(MTOT / 128, HID / 128, 1);
    gemm_kernel<1><<<gOUT, 256>>>(nullptr, Wo, bo, nullptr, nullptr, nullptr, nullptr, out);
}

// round 3
// speedup vs baseline: 1.1787x; 1.1787x over previous
#include <cuda_runtime.h>

#define HID   1024
#define NH    16
#define DK    64
#define BATCH 4
#define SEQ   2048
#define MTOT  (BATCH*SEQ)

typedef unsigned long long u64;

// ---- packed f32x2 helpers (Blackwell-only: fma.rn.f32x2 etc.) ----
__device__ __forceinline__ u64 pack2(float lo, float hi) {
    u64 r; asm("mov.b64 %0,{%1,%2};" : "=l"(r) : "f"(lo), "f"(hi)); return r;
}
__device__ __forceinline__ void unpack2(u64 v, float& lo, float& hi) {
    asm("mov.b64 {%0,%1},%2;" : "=f"(lo), "=f"(hi) : "l"(v));
}
__device__ __forceinline__ u64 fma2(u64 a, u64 b, u64 c) {
    u64 d; asm("fma.rn.f32x2 %0,%1,%2,%3;" : "=l"(d) : "l"(a), "l"(b), "l"(c)); return d;
}
__device__ __forceinline__ u64 add2(u64 a, u64 b) {
    u64 d; asm("add.rn.f32x2 %0,%1,%2;" : "=l"(d) : "l"(a), "l"(b)); return d;
}
__device__ __forceinline__ u64 mul2(u64 a, u64 b) {
    u64 d; asm("mul.rn.f32x2 %0,%1,%2;" : "=l"(d) : "l"(a), "l"(b)); return d;
}

// Scratch (allocation-free rule: __device__ globals)
__device__ float g_q[(size_t)BATCH*NH*SEQ*DK];   // [b,h,s,d], pre-scaled by 1/sqrt(dk)
__device__ float g_k[(size_t)BATCH*NH*SEQ*DK];
__device__ float g_v[(size_t)BATCH*NH*SEQ*DK];
__device__ float g_ctx[(size_t)MTOT*HID];        // [b,s,h*dk] for output projection

// ---------------------------------------------------------------------------
// Tiled SGEMM with packed f32x2 inner loop.
// Y[m][n] = sum_k X[m][k] * W[n][k] + bias[n]
// BM=BN=128, BK=16, 256 threads, 8x8 per-thread tile (as 8x4 f32x2 pairs).
// MODE 0: QKV projection (blockIdx.z selects matrix, scatter-store to g_q/g_k/g_v)
// MODE 1: output projection (X = g_ctx, plain store to OutPlain)
// ---------------------------------------------------------------------------
template<int MODE>
__global__ __launch_bounds__(256, 2)
void gemm_kernel(const float* __restrict__ Xin,
                 const float* __restrict__ W0, const float* __restrict__ B0,
                 const float* __restrict__ W1, const float* __restrict__ B1,
                 const float* __restrict__ W2, const float* __restrict__ B2,
                 float* __restrict__ OutPlain)
{
    const float* X = (MODE == 1) ? g_ctx : Xin;
    const int z = blockIdx.z;
    const float* W;
    const float* bias;
    if (MODE == 0) {
        W    = (z == 0) ? W0 : ((z == 1) ? W1 : W2);
        bias = (z == 0) ? B0 : ((z == 1) ? B1 : B2);
    } else {
        W = W0; bias = B0;
    }

    __shared__ float As[16][128];
    __shared__ float Bs[16][128];

    const int m0  = blockIdx.x * 128;
    const int n0  = blockIdx.y * 128;
    const int tid = threadIdx.x;
    const int tr  = tid >> 4;   // 0..15
    const int tc  = tid & 15;   // 0..15

    // acc2[i][jp]: i = m-subrow (8), jp = n-pair (4): pairs (j0,j1),(j2,j3),(j4,j5),(j6,j7)
    u64 acc2[8][4];
#pragma unroll
    for (int i = 0; i < 8; i++)
#pragma unroll
        for (int jp = 0; jp < 4; jp++) acc2[i][jp] = 0ull;   // bits of (0.f,0.f)

    const float* Ap = X + (size_t)m0 * HID;
    const float* Bp = W + (size_t)n0 * HID;

    for (int k0 = 0; k0 < HID; k0 += 16) {
#pragma unroll
        for (int u = 0; u < 2; u++) {
            int f   = tid + u * 256;          // 0..511 float4 slots (128 rows x 4 f4)
            int row = f >> 2;
            int c4  = (f & 3) << 2;
            float4 a = *(const float4*)(Ap + (size_t)row * HID + k0 + c4);
            As[c4 + 0][row] = a.x; As[c4 + 1][row] = a.y;
            As[c4 + 2][row] = a.z; As[c4 + 3][row] = a.w;
            float4 b = *(const float4*)(Bp + (size_t)row * HID + k0 + c4);
            Bs[c4 + 0][row] = b.x; Bs[c4 + 1][row] = b.y;
            Bs[c4 + 2][row] = b.z; Bs[c4 + 3][row] = b.w;
        }
        __syncthreads();

#pragma unroll
        for (int kk = 0; kk < 16; kk++) {
            float ra[8];
            *(float4*)&ra[0] = *(const float4*)&As[kk][(tr << 2)];
            *(float4*)&ra[4] = *(const float4*)&As[kk][64 + (tr << 2)];
            // B fragments as packed pairs straight out of shared memory
            ulonglong2 rbA = *(const ulonglong2*)&Bs[kk][(tc << 2)];        // (j0,j1),(j2,j3)
            ulonglong2 rbB = *(const ulonglong2*)&Bs[kk][64 + (tc << 2)];   // (j4,j5),(j6,j7)
#pragma unroll
            for (int i = 0; i < 8; i++) {
                u64 ra2 = pack2(ra[i], ra[i]);
                acc2[i][0] = fma2(ra2, rbA.x, acc2[i][0]);
                acc2[i][1] = fma2(ra2, rbA.y, acc2[i][1]);
                acc2[i][2] = fma2(ra2, rbB.x, acc2[i][2]);
                acc2[i][3] = fma2(ra2, rbB.y, acc2[i][3]);
            }
        }
        __syncthreads();
    }

#pragma unroll
    for (int i = 0; i < 8; i++) {
        int m = m0 + ((i >> 2) << 6) + (tr << 2) + (i & 3);
        // unpack into j order 0..7 (j0..j3 -> tc*4+j, j4..j7 -> 64+tc*4+(j-4))
        float rowf[8];
        unpack2(acc2[i][0], rowf[0], rowf[1]);
        unpack2(acc2[i][1], rowf[2], rowf[3]);
        unpack2(acc2[i][2], rowf[4], rowf[5]);
        unpack2(acc2[i][3], rowf[6], rowf[7]);
#pragma unroll
        for (int j = 0; j < 8; j++) {
            int n = n0 + ((j >> 2) << 6) + (tc << 2) + (j & 3);
            float val = rowf[j] + bias[n];
            if (MODE == 0) {
                float* dst = (z == 0) ? g_q : ((z == 1) ? g_k : g_v);
                if (z == 0) val *= 0.125f;   // 1/sqrt(64)
                int bb = m >> 11, s = m & 2047, hh = n >> 6, d = n & 63;
                dst[(((size_t)(bb * NH + hh)) * SEQ + s) * DK + d] = val;
            } else {
                OutPlain[(size_t)m * HID + n] = val;
            }
        }
    }
}

// ---------------------------------------------------------------------------
// Flash attention, packed f32x2 math: one thread per query row.
// K/V streamed through smem in 32-key chunks; per-thread score staging in
// padded smem; online softmax with chunk-max.
// ---------------------------------------------------------------------------
__global__ __launch_bounds__(128, 2)
void attn_kernel()
{
    const int b   = blockIdx.z;
    const int h   = blockIdx.y;
    const int tid = threadIdx.x;
    const int qi  = blockIdx.x * 128 + tid;

    const size_t bh = (size_t)(b * NH + h);
    const float* qp = g_q + (bh * SEQ + qi) * DK;
    const float* kb = g_k + bh * SEQ * DK;
    const float* vb = g_v + bh * SEQ * DK;

    __shared__ float Ks[32][64];
    __shared__ float Vs[32][64];
    __shared__ float Ss[128][33];   // padded: conflict-free per-thread rows

    // q as 32 packed pairs
    u64 q2[32];
    {
        const ulonglong2* qp2 = (const ulonglong2*)qp;
#pragma unroll
        for (int t = 0; t < 16; t++) { ulonglong2 v = qp2[t]; q2[2*t] = v.x; q2[2*t+1] = v.y; }
    }

    u64 acc2[32];
#pragma unroll
    for (int t = 0; t < 32; t++) acc2[t] = 0ull;
    float mrun = -1e30f, lrun = 0.f;

    for (int kc = 0; kc < SEQ; kc += 32) {
        // cooperative chunk load: 32 rows x 64 floats = 512 float4, contiguous
        const float4* ks = (const float4*)(kb + (size_t)kc * DK);
        const float4* vs = (const float4*)(vb + (size_t)kc * DK);
        float4* kd = (float4*)&Ks[0][0];
        float4* vd = (float4*)&Vs[0][0];
#pragma unroll
        for (int u = 0; u < 4; u++) {
            kd[tid + u * 128] = ks[tid + u * 128];
            vd[tid + u * 128] = vs[tid + u * 128];
        }
        __syncthreads();

        // ---- scores for this chunk + chunk max (packed dot products) ----
        float cmax = -1e30f;
#pragma unroll 2
        for (int j = 0; j < 32; j++) {
            const ulonglong2* krow = (const ulonglong2*)&Ks[j][0];   // 16 x 16B, broadcast LDS
            u64 s0 = 0ull, s1 = 0ull, s2 = 0ull, s3 = 0ull;
#pragma unroll
            for (int t = 0; t < 16; t += 2) {
                ulonglong2 kA = krow[t];
                ulonglong2 kB = krow[t + 1];
                s0 = fma2(q2[2*t    ], kA.x, s0);
                s1 = fma2(q2[2*t + 1], kA.y, s1);
                s2 = fma2(q2[2*t + 2], kB.x, s2);
                s3 = fma2(q2[2*t + 3], kB.y, s3);
            }
            u64 st = add2(add2(s0, s1), add2(s2, s3));
            float lo, hi; unpack2(st, lo, hi);
            float sum = lo + hi;
            Ss[tid][j] = sum;
            cmax = fmaxf(cmax, sum);
        }

        float newm = fmaxf(mrun, cmax);
        float corr = __expf(mrun - newm);   // 0 on first chunk
        mrun = newm;
        lrun *= corr;
        {
            u64 corr2 = pack2(corr, corr);
#pragma unroll
            for (int t = 0; t < 32; t++) acc2[t] = mul2(acc2[t], corr2);
        }

        // ---- p = exp(s - m); acc += p * V (packed) ----
#pragma unroll 2
        for (int j = 0; j < 32; j++) {
            float p = __expf(Ss[tid][j] - mrun);
            lrun += p;
            u64 p2 = pack2(p, p);
            const ulonglong2* vrow = (const ulonglong2*)&Vs[j][0];
#pragma unroll
            for (int t = 0; t < 16; t++) {
                ulonglong2 vv = vrow[t];
                acc2[2*t    ] = fma2(p2, vv.x, acc2[2*t    ]);
                acc2[2*t + 1] = fma2(p2, vv.y, acc2[2*t + 1]);
            }
        }
        __syncthreads();
    }

    const float inv = 1.f / lrun;
    const u64 inv2 = pack2(inv, inv);
    float* op = g_ctx + ((size_t)(b * SEQ) + qi) * HID + h * DK;
    ulonglong2* op2 = (ulonglong2*)op;
#pragma unroll
    for (int t = 0; t < 16; t++) {
        ulonglong2 r;
        r.x = mul2(acc2[2*t    ], inv2);
        r.y = mul2(acc2[2*t + 1], inv2);
        op2[t] = r;
    }
}

// ---------------------------------------------------------------------------
extern "C" void kernel_launch(void* const* d_in, const int* in_sizes, int n_in,
                              void* d_out, int out_size)
{
    (void)in_sizes; (void)n_in; (void)out_size;
    const float* tgt = (const float*)d_in[0];
    const float* Wq  = (const float*)d_in[1];
    const float* bq  = (const float*)d_in[2];
    const float* Wk  = (const float*)d_in[3];
    const float* bk  = (const float*)d_in[4];
    const float* Wv  = (const float*)d_in[5];
    const float* bv  = (const float*)d_in[6];
    const float* Wo  = (const float*)d_in[7];
    const float* bo  = (const float*)d_in[8];
    float* out = (float*)d_out;

    dim3 gQKV(MTOT / 128, HID / 128, 3);
    gemm_kernel<0><<<gQKV, 256>>>(tgt, Wq, bq, Wk, bk, Wv, bv, nullptr);

    dim3 gATT(SEQ / 128, NH, BATCH);
    attn_kernel<<<gATT, 128>>>();

    dim3 gOUT(MTOT / 128, HID / 128, 1);
    gemm_kernel<1><<<gOUT, 256>>>(nullptr, Wo, bo, nullptr, nullptr, nullptr, nullptr, out);
}

// round 6
// speedup vs baseline: 1.4997x; 1.2724x over previous
#include <cuda_runtime.h>
#include <cuda_bf16.h>
#include <cstdint>

#define HID   1024
#define NH    16
#define DK    64
#define BATCH 4
#define SEQ   2048
#define MTOT  (BATCH*SEQ)

typedef unsigned long long u64;

// ---- packed f32x2 helpers (attention kernel) ----
__device__ __forceinline__ u64 pack2(float lo, float hi) {
    u64 r; asm("mov.b64 %0,{%1,%2};" : "=l"(r) : "f"(lo), "f"(hi)); return r;
}
__device__ __forceinline__ void unpack2(u64 v, float& lo, float& hi) {
    asm("mov.b64 {%0,%1},%2;" : "=f"(lo), "=f"(hi) : "l"(v));
}
__device__ __forceinline__ u64 fma2(u64 a, u64 b, u64 c) {
    u64 d; asm("fma.rn.f32x2 %0,%1,%2,%3;" : "=l"(d) : "l"(a), "l"(b), "l"(c)); return d;
}
__device__ __forceinline__ u64 add2(u64 a, u64 b) {
    u64 d; asm("add.rn.f32x2 %0,%1,%2;" : "=l"(d) : "l"(a), "l"(b)); return d;
}
__device__ __forceinline__ u64 mul2(u64 a, u64 b) {
    u64 d; asm("mul.rn.f32x2 %0,%1,%2;" : "=l"(d) : "l"(a), "l"(b)); return d;
}

// ---- mma.sync / ldmatrix helpers (base compute_100 features) ----
__device__ __forceinline__ uint32_t smem_to_u32(const void* p) {
    uint32_t a;
    asm("{ .reg .u64 t; cvta.to.shared.u64 t, %1; cvt.u32.u64 %0, t; }" : "=r"(a) : "l"(p));
    return a;
}
#define LDSM4(r0, r1, r2, r3, addr) \
    asm volatile("ldmatrix.sync.aligned.m8n8.x4.shared.b16 {%0,%1,%2,%3},[%4];" \
        : "=r"(r0), "=r"(r1), "=r"(r2), "=r"(r3) : "r"(addr))
#define MMA16816(c, a, b) \
    asm volatile("mma.sync.aligned.m16n8k16.row.col.f32.bf16.bf16.f32 " \
        "{%0,%1,%2,%3},{%4,%5,%6,%7},{%8,%9},{%0,%1,%2,%3};" \
        : "+f"((c)[0]), "+f"((c)[1]), "+f"((c)[2]), "+f"((c)[3]) \
        : "r"((a)[0]), "r"((a)[1]), "r"((a)[2]), "r"((a)[3]), "r"((b)[0]), "r"((b)[1]))

// bf16 2-term split: x ~= hi + lo (each bf16); error ~2^-17 relative
__device__ __forceinline__ void bf16split(float x, __nv_bfloat16& h, __nv_bfloat16& l) {
    h = __float2bfloat16_rn(x);
    l = __float2bfloat16_rn(x - __bfloat162float(h));
}

// Scratch (allocation-free rule: __device__ globals)
__device__ float g_q[(size_t)BATCH*NH*SEQ*DK];   // [b,h,s,d], pre-scaled by 1/sqrt(dk)
__device__ float g_k[(size_t)BATCH*NH*SEQ*DK];
__device__ float g_v[(size_t)BATCH*NH*SEQ*DK];
__device__ float g_ctx[(size_t)MTOT*HID];        // [b,s,h*dk] for output projection

// ---------------------------------------------------------------------------
// bf16-split tensor-core GEMM: Y[m][n] = sum_k X[m][k]*W[n][k] + bias[n]
// CTA tile 128x128, BK=32, 8 warps (2x4), warp tile 64x32.
// D = Ahi*Bhi + Ahi*Blo + Alo*Bhi  (fp32 accumulate in mma)
// MODE 0: QKV projection (z selects W; scatter to g_q/g_k/g_v; q scaled)
// MODE 1: output projection (X = g_ctx, plain store)
// ---------------------------------------------------------------------------
#define BK      32
#define NKT     (HID / BK)          // 32
#define KPAD    40                  // bf16 per padded row (80 bytes)
#define PLANE   (128 * KPAD)        // bf16 elements per plane
#define STG     (4 * PLANE)         // Ahi, Alo, Bhi, Blo
#define GEMM_SMEM (2 * STG * 2)     // bytes (2 stages, 2B/elt) = 81920

template<int MODE>
__global__ __launch_bounds__(256)
void gemm_mma(const float* __restrict__ Xin,
              const float* __restrict__ W0, const float* __restrict__ B0,
              const float* __restrict__ W1, const float* __restrict__ B1,
              const float* __restrict__ W2, const float* __restrict__ B2,
              float* __restrict__ OutPlain)
{
    extern __shared__ __nv_bfloat16 sm[];
    const uint32_t smb = smem_to_u32(sm);

    const float* X = (MODE == 1) ? g_ctx : Xin;
    const int z = blockIdx.z;
    const float* W;
    const float* bias;
    if (MODE == 0) {
        W    = (z == 0) ? W0 : ((z == 1) ? W1 : W2);
        bias = (z == 0) ? B0 : ((z == 1) ? B1 : B2);
    } else {
        W = W0; bias = B0;
    }

    const int m0   = blockIdx.x * 128;
    const int n0   = blockIdx.y * 128;
    const int tid  = threadIdx.x;
    const int wid  = tid >> 5;
    const int lane = tid & 31;
    const int warp_m = (wid >> 2) * 64;   // 0 or 64
    const int warp_n = (wid & 3) * 32;    // 0,32,64,96

    // ---- global->reg->smem staging (each thread: one A half-row + one B half-row)
    const int rowL = tid >> 1;            // 0..127
    const int colf = (tid & 1) << 4;      // 0 or 16 (floats)
    const float* aSrc = X + (size_t)(m0 + rowL) * HID + colf;
    const float* bSrc = W + (size_t)(n0 + rowL) * HID + colf;

    float4 ra[4], rb[4];
    auto G2R = [&](int kt) {
        const float* a = aSrc + kt * BK;
        const float* b = bSrc + kt * BK;
#pragma unroll
        for (int i = 0; i < 4; i++) {
            ra[i] = *(const float4*)(a + i * 4);
            rb[i] = *(const float4*)(b + i * 4);
        }
    };
    auto R2S = [&](int s) {
        __nv_bfloat162* Ah = (__nv_bfloat162*)(sm + s * STG + 0 * PLANE + rowL * KPAD + colf);
        __nv_bfloat162* Al = (__nv_bfloat162*)(sm + s * STG + 1 * PLANE + rowL * KPAD + colf);
        __nv_bfloat162* Bh = (__nv_bfloat162*)(sm + s * STG + 2 * PLANE + rowL * KPAD + colf);
        __nv_bfloat162* Bl = (__nv_bfloat162*)(sm + s * STG + 3 * PLANE + rowL * KPAD + colf);
#pragma unroll
        for (int i = 0; i < 4; i++) {
            __nv_bfloat16 hx, lx, hy, ly, hz, lz, hw, lw;
            bf16split(ra[i].x, hx, lx); bf16split(ra[i].y, hy, ly);
            bf16split(ra[i].z, hz, lz); bf16split(ra[i].w, hw, lw);
            Ah[i*2] = __nv_bfloat162(hx, hy); Ah[i*2+1] = __nv_bfloat162(hz, hw);
            Al[i*2] = __nv_bfloat162(lx, ly); Al[i*2+1] = __nv_bfloat162(lz, lw);
            bf16split(rb[i].x, hx, lx); bf16split(rb[i].y, hy, ly);
            bf16split(rb[i].z, hz, lz); bf16split(rb[i].w, hw, lw);
            Bh[i*2] = __nv_bfloat162(hx, hy); Bh[i*2+1] = __nv_bfloat162(hz, hw);
            Bl[i*2] = __nv_bfloat162(lx, ly); Bl[i*2+1] = __nv_bfloat162(lz, lw);
        }
    };

    float acc[4][4][4];
#pragma unroll
    for (int mt = 0; mt < 4; mt++)
#pragma unroll
        for (int nt = 0; nt < 4; nt++)
#pragma unroll
            for (int e = 0; e < 4; e++) acc[mt][nt][e] = 0.f;

    // ldmatrix per-lane address components
    const int arow = warp_m + (lane & 15);
    const int acolL = (lane >> 4) * 8;                       // +0/+8 within k16
    const int brow = warp_n + ((lane >> 4) & 1) * 8 + (lane & 7);
    const int bcolL = ((lane >> 3) & 1) * 8;

    G2R(0); R2S(0);
    __syncthreads();

    for (int kt = 0; kt < NKT; kt++) {
        const int s = kt & 1;
        if (kt + 1 < NKT) G2R(kt + 1);

        const uint32_t sb = smb + (uint32_t)(s * STG) * 2;
        uint32_t ahi[4][4], alo[4][4], bhi[4][2], blo[4][2];
#pragma unroll
        for (int sub = 0; sub < 2; sub++) {
            const int kks = sub * 16;
#pragma unroll
            for (int mt = 0; mt < 4; mt++) {
                uint32_t ad = sb + (uint32_t)(((arow + mt * 16) * KPAD) + kks + acolL) * 2;
                LDSM4(ahi[mt][0], ahi[mt][1], ahi[mt][2], ahi[mt][3], ad);
                LDSM4(alo[mt][0], alo[mt][1], alo[mt][2], alo[mt][3], ad + PLANE * 2);
            }
#pragma unroll
            for (int p = 0; p < 2; p++) {
                uint32_t bd = sb + (uint32_t)(2 * PLANE + ((brow + p * 16) * KPAD) + kks + bcolL) * 2;
                LDSM4(bhi[2*p][0], bhi[2*p][1], bhi[2*p+1][0], bhi[2*p+1][1], bd);
                LDSM4(blo[2*p][0], blo[2*p][1], blo[2*p+1][0], blo[2*p+1][1], bd + PLANE * 2);
            }
#pragma unroll
            for (int mt = 0; mt < 4; mt++)
#pragma unroll
                for (int nt = 0; nt < 4; nt++) {
                    MMA16816(acc[mt][nt], ahi[mt], bhi[nt]);
                    MMA16816(acc[mt][nt], ahi[mt], blo[nt]);
                    MMA16816(acc[mt][nt], alo[mt], bhi[nt]);
                }
        }

        if (kt + 1 < NKT) R2S((kt + 1) & 1);
        __syncthreads();
    }

    // ---- epilogue: c frag mapping (m16n8): rows g/g+8, cols tg*2, tg*2+1
    const int g  = lane >> 2;
    const int tg = lane & 3;
#pragma unroll
    for (int mt = 0; mt < 4; mt++) {
        const int m1 = m0 + warp_m + mt * 16 + g;
        const int m2 = m1 + 8;
#pragma unroll
        for (int nt = 0; nt < 4; nt++) {
            const int n = n0 + warp_n + nt * 8 + tg * 2;
            const float bv0 = __ldg(bias + n);
            const float bv1 = __ldg(bias + n + 1);
            const float* c = acc[mt][nt];
            if (MODE == 0) {
                float* dst = (z == 0) ? g_q : ((z == 1) ? g_k : g_v);
                const float qs = (z == 0) ? 0.125f : 1.0f;
                const int hh = n >> 6, d = n & 63;
                float2 v;
                v.x = (c[0] + bv0) * qs; v.y = (c[1] + bv1) * qs;
                *(float2*)(dst + (((size_t)((m1 >> 11) * NH + hh)) * SEQ + (m1 & 2047)) * DK + d) = v;
                v.x = (c[2] + bv0) * qs; v.y = (c[3] + bv1) * qs;
                *(float2*)(dst + (((size_t)((m2 >> 11) * NH + hh)) * SEQ + (m2 & 2047)) * DK + d) = v;
            } else {
                float2 v;
                v.x = c[0] + bv0; v.y = c[1] + bv1;
                *(float2*)(OutPlain + (size_t)m1 * HID + n) = v;
                v.x = c[2] + bv0; v.y = c[3] + bv1;
                *(float2*)(OutPlain + (size_t)m2 * HID + n) = v;
            }
        }
    }
}

// ---------------------------------------------------------------------------
// Flash attention, packed f32x2 math (unchanged from passing R3 version)
// ---------------------------------------------------------------------------
__global__ __launch_bounds__(128, 2)
void attn_kernel()
{
    const int b   = blockIdx.z;
    const int h   = blockIdx.y;
    const int tid = threadIdx.x;
    const int qi  = blockIdx.x * 128 + tid;

    const size_t bh = (size_t)(b * NH + h);
    const float* qp = g_q + (bh * SEQ + qi) * DK;
    const float* kb = g_k + bh * SEQ * DK;
    const float* vb = g_v + bh * SEQ * DK;

    __shared__ float Ks[32][64];
    __shared__ float Vs[32][64];
    __shared__ float Ss[128][33];

    u64 q2[32];
    {
        const ulonglong2* qp2 = (const ulonglong2*)qp;
#pragma unroll
        for (int t = 0; t < 16; t++) { ulonglong2 v = qp2[t]; q2[2*t] = v.x; q2[2*t+1] = v.y; }
    }

    u64 acc2[32];
#pragma unroll
    for (int t = 0; t < 32; t++) acc2[t] = 0ull;
    float mrun = -1e30f, lrun = 0.f;

    for (int kc = 0; kc < SEQ; kc += 32) {
        const float4* ks = (const float4*)(kb + (size_t)kc * DK);
        const float4* vs = (const float4*)(vb + (size_t)kc * DK);
        float4* kd = (float4*)&Ks[0][0];
        float4* vd = (float4*)&Vs[0][0];
#pragma unroll
        for (int u = 0; u < 4; u++) {
            kd[tid + u * 128] = ks[tid + u * 128];
            vd[tid + u * 128] = vs[tid + u * 128];
        }
        __syncthreads();

        float cmax = -1e30f;
#pragma unroll 2
        for (int j = 0; j < 32; j++) {
            const ulonglong2* krow = (const ulonglong2*)&Ks[j][0];
            u64 s0 = 0ull, s1 = 0ull, s2 = 0ull, s3 = 0ull;
#pragma unroll
            for (int t = 0; t < 16; t += 2) {
                ulonglong2 kA = krow[t];
                ulonglong2 kB = krow[t + 1];
                s0 = fma2(q2[2*t    ], kA.x, s0);
                s1 = fma2(q2[2*t + 1], kA.y, s1);
                s2 = fma2(q2[2*t + 2], kB.x, s2);
                s3 = fma2(q2[2*t + 3], kB.y, s3);
            }
            u64 st = add2(add2(s0, s1), add2(s2, s3));
            float lo, hi; unpack2(st, lo, hi);
            float sum = lo + hi;
            Ss[tid][j] = sum;
            cmax = fmaxf(cmax, sum);
        }

        float newm = fmaxf(mrun, cmax);
        float corr = __expf(mrun - newm);
        mrun = newm;
        lrun *= corr;
        {
            u64 corr2 = pack2(corr, corr);
#pragma unroll
            for (int t = 0; t < 32; t++) acc2[t] = mul2(acc2[t], corr2);
        }

#pragma unroll 2
        for (int j = 0; j < 32; j++) {
            float p = __expf(Ss[tid][j] - mrun);
            lrun += p;
            u64 p2 = pack2(p, p);
            const ulonglong2* vrow = (const ulonglong2*)&Vs[j][0];
#pragma unroll
            for (int t = 0; t < 16; t++) {
                ulonglong2 vv = vrow[t];
                acc2[2*t    ] = fma2(p2, vv.x, acc2[2*t    ]);
                acc2[2*t + 1] = fma2(p2, vv.y, acc2[2*t + 1]);
            }
        }
        __syncthreads();
    }

    const float inv = 1.f / lrun;
    const u64 inv2 = pack2(inv, inv);
    float* op = g_ctx + ((size_t)(b * SEQ) + qi) * HID + h * DK;
    ulonglong2* op2 = (ulonglong2*)op;
#pragma unroll
    for (int t = 0; t < 16; t++) {
        ulonglong2 r;
        r.x = mul2(acc2[2*t    ], inv2);
        r.y = mul2(acc2[2*t + 1], inv2);
        op2[t] = r;
    }
}

// ---------------------------------------------------------------------------
extern "C" void kernel_launch(void* const* d_in, const int* in_sizes, int n_in,
                              void* d_out, int out_size)
{
    (void)in_sizes; (void)n_in; (void)out_size;
    const float* tgt = (const float*)d_in[0];
    const float* Wq  = (const float*)d_in[1];
    const float* bq  = (const float*)d_in[2];
    const float* Wk  = (const float*)d_in[3];
    const float* bk  = (const float*)d_in[4];
    const float* Wv  = (const float*)d_in[5];
    const float* bv  = (const float*)d_in[6];
    const float* Wo  = (const float*)d_in[7];
    const float* bo  = (const float*)d_in[8];
    float* out = (float*)d_out;

    cudaFuncSetAttribute(gemm_mma<0>, cudaFuncAttributeMaxDynamicSharedMemorySize, GEMM_SMEM);
    cudaFuncSetAttribute(gemm_mma<1>, cudaFuncAttributeMaxDynamicSharedMemorySize, GEMM_SMEM);

    dim3 gQKV(MTOT / 128, HID / 128, 3);
    gemm_mma<0><<<gQKV, 256, GEMM_SMEM>>>(tgt, Wq, bq, Wk, bk, Wv, bv, nullptr);

    dim3 gATT(SEQ / 128, NH, BATCH);
    attn_kernel<<<gATT, 128>>>();

    dim3 gOUT(MTOT / 128, HID / 128, 1);
    gemm_mma<1><<<gOUT, 256, GEMM_SMEM>>>(nullptr, Wo, bo, nullptr, nullptr, nullptr, nullptr, out);
}

// round 7
// speedup vs baseline: 2.4660x; 1.6443x over previous
#include <cuda_runtime.h>
#include <cuda_bf16.h>
#include <cstdint>

#define HID   1024
#define NH    16
#define DK    64
#define BATCH 4
#define SEQ   2048
#define MTOT  (BATCH*SEQ)

// ---- mma.sync / ldmatrix helpers (base compute_100 features) ----
__device__ __forceinline__ uint32_t smem_to_u32(const void* p) {
    uint32_t a;
    asm("{ .reg .u64 t; cvta.to.shared.u64 t, %1; cvt.u32.u64 %0, t; }" : "=r"(a) : "l"(p));
    return a;
}
#define LDSM4(r0, r1, r2, r3, addr) \
    asm volatile("ldmatrix.sync.aligned.m8n8.x4.shared.b16 {%0,%1,%2,%3},[%4];" \
        : "=r"(r0), "=r"(r1), "=r"(r2), "=r"(r3) : "r"(addr))
#define LDSM4T(r0, r1, r2, r3, addr) \
    asm volatile("ldmatrix.sync.aligned.m8n8.x4.trans.shared.b16 {%0,%1,%2,%3},[%4];" \
        : "=r"(r0), "=r"(r1), "=r"(r2), "=r"(r3) : "r"(addr))
#define MMA16816(c, a, b) \
    asm volatile("mma.sync.aligned.m16n8k16.row.col.f32.bf16.bf16.f32 " \
        "{%0,%1,%2,%3},{%4,%5,%6,%7},{%8,%9},{%0,%1,%2,%3};" \
        : "+f"((c)[0]), "+f"((c)[1]), "+f"((c)[2]), "+f"((c)[3]) \
        : "r"((a)[0]), "r"((a)[1]), "r"((a)[2]), "r"((a)[3]), "r"((b)[0]), "r"((b)[1]))

// bf16 2-term split helpers
__device__ __forceinline__ void bf16split(float x, __nv_bfloat16& h, __nv_bfloat16& l) {
    h = __float2bfloat16_rn(x);
    l = __float2bfloat16_rn(x - __bfloat162float(h));
}
__device__ __forceinline__ uint32_t pkbf(__nv_bfloat16 a, __nv_bfloat16 b) {
    __nv_bfloat162 t(a, b);           // a -> low half
    return *(uint32_t*)&t;
}
// pack hi/lo of two floats
__device__ __forceinline__ void pk2split(float x, float y, uint32_t& h, uint32_t& l) {
    __nv_bfloat16 hx, lx, hy, ly;
    bf16split(x, hx, lx); bf16split(y, hy, ly);
    h = pkbf(hx, hy); l = pkbf(lx, ly);
}

// Scratch (allocation-free rule: __device__ globals)
__device__ float g_q[(size_t)BATCH*NH*SEQ*DK];   // [b,h,s,d], pre-scaled by 1/sqrt(dk)
__device__ float g_k[(size_t)BATCH*NH*SEQ*DK];
__device__ float g_v[(size_t)BATCH*NH*SEQ*DK];
__device__ float g_ctx[(size_t)MTOT*HID];        // [b,s,h*dk] for output projection

// ---------------------------------------------------------------------------
// bf16-split tensor-core GEMM (validated R6): Y = X W^T + bias
// ---------------------------------------------------------------------------
#define BK      32
#define NKT     (HID / BK)
#define KPAD    40
#define PLANE   (128 * KPAD)
#define STG     (4 * PLANE)
#define GEMM_SMEM (2 * STG * 2)

template<int MODE>
__global__ __launch_bounds__(256)
void gemm_mma(const float* __restrict__ Xin,
              const float* __restrict__ W0, const float* __restrict__ B0,
              const float* __restrict__ W1, const float* __restrict__ B1,
              const float* __restrict__ W2, const float* __restrict__ B2,
              float* __restrict__ OutPlain)
{
    extern __shared__ __nv_bfloat16 sm[];
    const uint32_t smb = smem_to_u32(sm);

    const float* X = (MODE == 1) ? g_ctx : Xin;
    const int z = blockIdx.z;
    const float* W;
    const float* bias;
    if (MODE == 0) {
        W    = (z == 0) ? W0 : ((z == 1) ? W1 : W2);
        bias = (z == 0) ? B0 : ((z == 1) ? B1 : B2);
    } else {
        W = W0; bias = B0;
    }

    const int m0   = blockIdx.x * 128;
    const int n0   = blockIdx.y * 128;
    const int tid  = threadIdx.x;
    const int wid  = tid >> 5;
    const int lane = tid & 31;
    const int warp_m = (wid >> 2) * 64;
    const int warp_n = (wid & 3) * 32;

    const int rowL = tid >> 1;
    const int colf = (tid & 1) << 4;
    const float* aSrc = X + (size_t)(m0 + rowL) * HID + colf;
    const float* bSrc = W + (size_t)(n0 + rowL) * HID + colf;

    float4 ra[4], rb[4];
    auto G2R = [&](int kt) {
        const float* a = aSrc + kt * BK;
        const float* b = bSrc + kt * BK;
#pragma unroll
        for (int i = 0; i < 4; i++) {
            ra[i] = *(const float4*)(a + i * 4);
            rb[i] = *(const float4*)(b + i * 4);
        }
    };
    auto R2S = [&](int s) {
        __nv_bfloat162* Ah = (__nv_bfloat162*)(sm + s * STG + 0 * PLANE + rowL * KPAD + colf);
        __nv_bfloat162* Al = (__nv_bfloat162*)(sm + s * STG + 1 * PLANE + rowL * KPAD + colf);
        __nv_bfloat162* Bh = (__nv_bfloat162*)(sm + s * STG + 2 * PLANE + rowL * KPAD + colf);
        __nv_bfloat162* Bl = (__nv_bfloat162*)(sm + s * STG + 3 * PLANE + rowL * KPAD + colf);
#pragma unroll
        for (int i = 0; i < 4; i++) {
            __nv_bfloat16 hx, lx, hy, ly, hz, lz, hw, lw;
            bf16split(ra[i].x, hx, lx); bf16split(ra[i].y, hy, ly);
            bf16split(ra[i].z, hz, lz); bf16split(ra[i].w, hw, lw);
            Ah[i*2] = __nv_bfloat162(hx, hy); Ah[i*2+1] = __nv_bfloat162(hz, hw);
            Al[i*2] = __nv_bfloat162(lx, ly); Al[i*2+1] = __nv_bfloat162(lz, lw);
            bf16split(rb[i].x, hx, lx); bf16split(rb[i].y, hy, ly);
            bf16split(rb[i].z, hz, lz); bf16split(rb[i].w, hw, lw);
            Bh[i*2] = __nv_bfloat162(hx, hy); Bh[i*2+1] = __nv_bfloat162(hz, hw);
            Bl[i*2] = __nv_bfloat162(lx, ly); Bl[i*2+1] = __nv_bfloat162(lz, lw);
        }
    };

    float acc[4][4][4];
#pragma unroll
    for (int mt = 0; mt < 4; mt++)
#pragma unroll
        for (int nt = 0; nt < 4; nt++)
#pragma unroll
            for (int e = 0; e < 4; e++) acc[mt][nt][e] = 0.f;

    const int arow = warp_m + (lane & 15);
    const int acolL = (lane >> 4) * 8;
    const int brow = warp_n + ((lane >> 4) & 1) * 8 + (lane & 7);
    const int bcolL = ((lane >> 3) & 1) * 8;

    G2R(0); R2S(0);
    __syncthreads();

    for (int kt = 0; kt < NKT; kt++) {
        const int s = kt & 1;
        if (kt + 1 < NKT) G2R(kt + 1);

        const uint32_t sb = smb + (uint32_t)(s * STG) * 2;
        uint32_t ahi[4][4], alo[4][4], bhi[4][2], blo[4][2];
#pragma unroll
        for (int sub = 0; sub < 2; sub++) {
            const int kks = sub * 16;
#pragma unroll
            for (int mt = 0; mt < 4; mt++) {
                uint32_t ad = sb + (uint32_t)(((arow + mt * 16) * KPAD) + kks + acolL) * 2;
                LDSM4(ahi[mt][0], ahi[mt][1], ahi[mt][2], ahi[mt][3], ad);
                LDSM4(alo[mt][0], alo[mt][1], alo[mt][2], alo[mt][3], ad + PLANE * 2);
            }
#pragma unroll
            for (int p = 0; p < 2; p++) {
                uint32_t bd = sb + (uint32_t)(2 * PLANE + ((brow + p * 16) * KPAD) + kks + bcolL) * 2;
                LDSM4(bhi[2*p][0], bhi[2*p][1], bhi[2*p+1][0], bhi[2*p+1][1], bd);
                LDSM4(blo[2*p][0], blo[2*p][1], blo[2*p+1][0], blo[2*p+1][1], bd + PLANE * 2);
            }
#pragma unroll
            for (int mt = 0; mt < 4; mt++)
#pragma unroll
                for (int nt = 0; nt < 4; nt++) {
                    MMA16816(acc[mt][nt], ahi[mt], bhi[nt]);
                    MMA16816(acc[mt][nt], ahi[mt], blo[nt]);
                    MMA16816(acc[mt][nt], alo[mt], bhi[nt]);
                }
        }

        if (kt + 1 < NKT) R2S((kt + 1) & 1);
        __syncthreads();
    }

    const int g  = lane >> 2;
    const int tg = lane & 3;
#pragma unroll
    for (int mt = 0; mt < 4; mt++) {
        const int m1 = m0 + warp_m + mt * 16 + g;
        const int m2 = m1 + 8;
#pragma unroll
        for (int nt = 0; nt < 4; nt++) {
            const int n = n0 + warp_n + nt * 8 + tg * 2;
            const float bv0 = __ldg(bias + n);
            const float bv1 = __ldg(bias + n + 1);
            const float* c = acc[mt][nt];
            if (MODE == 0) {
                float* dst = (z == 0) ? g_q : ((z == 1) ? g_k : g_v);
                const float qs = (z == 0) ? 0.125f : 1.0f;
                const int hh = n >> 6, d = n & 63;
                float2 v;
                v.x = (c[0] + bv0) * qs; v.y = (c[1] + bv1) * qs;
                *(float2*)(dst + (((size_t)((m1 >> 11) * NH + hh)) * SEQ + (m1 & 2047)) * DK + d) = v;
                v.x = (c[2] + bv0) * qs; v.y = (c[3] + bv1) * qs;
                *(float2*)(dst + (((size_t)((m2 >> 11) * NH + hh)) * SEQ + (m2 & 2047)) * DK + d) = v;
            } else {
                float2 v;
                v.x = c[0] + bv0; v.y = c[1] + bv1;
                *(float2*)(OutPlain + (size_t)m1 * HID + n) = v;
                v.x = c[2] + bv0; v.y = c[3] + bv1;
                *(float2*)(OutPlain + (size_t)m2 * HID + n) = v;
            }
        }
    }
}

// ---------------------------------------------------------------------------
// Flash attention on tensor cores, bf16-split everywhere.
// CTA: 128 queries, 8 warps (16 q-rows each). Key chunks of 64.
// S = Q K^T (3 mma products), online softmax in c-frag layout, P.V (3 products).
// ---------------------------------------------------------------------------
#define SC    64
#define QB    128
#define DPAD  72   // padded bf16 row for K/V smem (144B: conflict-free ldmatrix)

__global__ __launch_bounds__(256)
void attn_mma()
{
    __shared__ __nv_bfloat16 Kh[SC][DPAD], Kl[SC][DPAD], Vh[SC][DPAD], Vl[SC][DPAD];

    const int b    = blockIdx.z;
    const int h    = blockIdx.y;
    const int tid  = threadIdx.x;
    const int wid  = tid >> 5;
    const int lane = tid & 31;
    const int g    = lane >> 2;
    const int tg   = lane & 3;

    const size_t bh = (size_t)(b * NH + h);
    const int qrow0 = blockIdx.x * QB + wid * 16;

    const uint32_t smK = smem_to_u32(&Kh[0][0]);
    const uint32_t smKl = smem_to_u32(&Kl[0][0]);
    const uint32_t smV = smem_to_u32(&Vh[0][0]);
    const uint32_t smVl = smem_to_u32(&Vl[0][0]);

    // ---- Q a-frags (hi/lo), loaded once from gmem ----
    uint32_t qa_h[4][4], qa_l[4][4];
    {
        const float* q0 = g_q + (bh * SEQ + qrow0 + g) * DK;
        const float* q8 = q0 + 8 * DK;
#pragma unroll
        for (int kk = 0; kk < 4; kk++) {
            float2 v;
            v = *(const float2*)(q0 + kk * 16 + 2 * tg);
            pk2split(v.x, v.y, qa_h[kk][0], qa_l[kk][0]);
            v = *(const float2*)(q8 + kk * 16 + 2 * tg);
            pk2split(v.x, v.y, qa_h[kk][1], qa_l[kk][1]);
            v = *(const float2*)(q0 + kk * 16 + 8 + 2 * tg);
            pk2split(v.x, v.y, qa_h[kk][2], qa_l[kk][2]);
            v = *(const float2*)(q8 + kk * 16 + 8 + 2 * tg);
            pk2split(v.x, v.y, qa_h[kk][3], qa_l[kk][3]);
        }
    }

    float o[8][4];
#pragma unroll
    for (int d = 0; d < 8; d++)
#pragma unroll
        for (int e = 0; e < 4; e++) o[d][e] = 0.f;
    float mrun0 = -1e30f, mrun1 = -1e30f, lrun0 = 0.f, lrun1 = 0.f;

    // cooperative loader indices: 256 threads, 64 rows x 64 floats per matrix
    const int lrow = tid >> 2;            // 0..63
    const int lcol = (tid & 3) * 16;      // 0,16,32,48
    const float* kbase = g_k + bh * SEQ * DK;
    const float* vbase = g_v + bh * SEQ * DK;

    // ldmatrix address components
    const int kRow = ((lane >> 4) & 1) * 8 + (lane & 7);   // + p*16
    const int kColH = ((lane >> 3) & 1) * 8;               // + kk*16
    const int vRow = ((lane >> 3) & 1) * 8 + (lane & 7);   // + kk2*16
    const int vColH = (lane >> 4) * 8;                     // + e*16

    for (int kc = 0; kc < SEQ; kc += SC) {
        // ---- stage K/V chunk: fp32 -> bf16 hi/lo smem ----
        {
            const float* ksrc = kbase + (size_t)(kc + lrow) * DK + lcol;
            const float* vsrc = vbase + (size_t)(kc + lrow) * DK + lcol;
#pragma unroll
            for (int i = 0; i < 4; i++) {
                float4 v = *(const float4*)(ksrc + i * 4);
                __nv_bfloat16 hh, ll;
                bf16split(v.x, hh, ll); Kh[lrow][lcol+i*4+0] = hh; Kl[lrow][lcol+i*4+0] = ll;
                bf16split(v.y, hh, ll); Kh[lrow][lcol+i*4+1] = hh; Kl[lrow][lcol+i*4+1] = ll;
                bf16split(v.z, hh, ll); Kh[lrow][lcol+i*4+2] = hh; Kl[lrow][lcol+i*4+2] = ll;
                bf16split(v.w, hh, ll); Kh[lrow][lcol+i*4+3] = hh; Kl[lrow][lcol+i*4+3] = ll;
                v = *(const float4*)(vsrc + i * 4);
                bf16split(v.x, hh, ll); Vh[lrow][lcol+i*4+0] = hh; Vl[lrow][lcol+i*4+0] = ll;
                bf16split(v.y, hh, ll); Vh[lrow][lcol+i*4+1] = hh; Vl[lrow][lcol+i*4+1] = ll;
                bf16split(v.z, hh, ll); Vh[lrow][lcol+i*4+2] = hh; Vl[lrow][lcol+i*4+2] = ll;
                bf16split(v.w, hh, ll); Vh[lrow][lcol+i*4+3] = hh; Vl[lrow][lcol+i*4+3] = ll;
            }
        }
        __syncthreads();

        // ---- S = Q K^T ----
        float s[8][4];
#pragma unroll
        for (int j = 0; j < 8; j++)
#pragma unroll
            for (int e = 0; e < 4; e++) s[j][e] = 0.f;

#pragma unroll
        for (int kk = 0; kk < 4; kk++) {
            uint32_t kbh[8][2], kbl[8][2];
#pragma unroll
            for (int p = 0; p < 4; p++) {
                uint32_t off = (uint32_t)(((p * 16 + kRow) * DPAD) + kk * 16 + kColH) * 2;
                LDSM4(kbh[2*p][0], kbh[2*p][1], kbh[2*p+1][0], kbh[2*p+1][1], smK + off);
                LDSM4(kbl[2*p][0], kbl[2*p][1], kbl[2*p+1][0], kbl[2*p+1][1], smKl + off);
            }
#pragma unroll
            for (int j = 0; j < 8; j++) {
                MMA16816(s[j], qa_h[kk], kbh[j]);
                MMA16816(s[j], qa_h[kk], kbl[j]);
                MMA16816(s[j], qa_l[kk], kbh[j]);
            }
        }

        // ---- online softmax in c-frag layout ----
        float mx0 = -1e30f, mx1 = -1e30f;
#pragma unroll
        for (int j = 0; j < 8; j++) {
            mx0 = fmaxf(mx0, fmaxf(s[j][0], s[j][1]));
            mx1 = fmaxf(mx1, fmaxf(s[j][2], s[j][3]));
        }
        mx0 = fmaxf(mx0, __shfl_xor_sync(0xffffffff, mx0, 1));
        mx0 = fmaxf(mx0, __shfl_xor_sync(0xffffffff, mx0, 2));
        mx1 = fmaxf(mx1, __shfl_xor_sync(0xffffffff, mx1, 1));
        mx1 = fmaxf(mx1, __shfl_xor_sync(0xffffffff, mx1, 2));

        const float nm0 = fmaxf(mrun0, mx0);
        const float nm1 = fmaxf(mrun1, mx1);
        const float corr0 = __expf(mrun0 - nm0);
        const float corr1 = __expf(mrun1 - nm1);
        mrun0 = nm0; mrun1 = nm1;

        float sum0 = 0.f, sum1 = 0.f;
#pragma unroll
        for (int j = 0; j < 8; j++) {
            s[j][0] = __expf(s[j][0] - nm0); sum0 += s[j][0];
            s[j][1] = __expf(s[j][1] - nm0); sum0 += s[j][1];
            s[j][2] = __expf(s[j][2] - nm1); sum1 += s[j][2];
            s[j][3] = __expf(s[j][3] - nm1); sum1 += s[j][3];
        }
        sum0 += __shfl_xor_sync(0xffffffff, sum0, 1);
        sum0 += __shfl_xor_sync(0xffffffff, sum0, 2);
        sum1 += __shfl_xor_sync(0xffffffff, sum1, 1);
        sum1 += __shfl_xor_sync(0xffffffff, sum1, 2);
        lrun0 = lrun0 * corr0 + sum0;
        lrun1 = lrun1 * corr1 + sum1;

#pragma unroll
        for (int d = 0; d < 8; d++) {
            o[d][0] *= corr0; o[d][1] *= corr0;
            o[d][2] *= corr1; o[d][3] *= corr1;
        }

        // ---- pack P to bf16 hi/lo a-frags (c-layout == a-layout) ----
        uint32_t pa_h[4][4], pa_l[4][4];
#pragma unroll
        for (int kk2 = 0; kk2 < 4; kk2++) {
            const int jL = 2 * kk2, jH = 2 * kk2 + 1;
            pk2split(s[jL][0], s[jL][1], pa_h[kk2][0], pa_l[kk2][0]);
            pk2split(s[jL][2], s[jL][3], pa_h[kk2][1], pa_l[kk2][1]);
            pk2split(s[jH][0], s[jH][1], pa_h[kk2][2], pa_l[kk2][2]);
            pk2split(s[jH][2], s[jH][3], pa_h[kk2][3], pa_l[kk2][3]);
        }

        // ---- O += P V ----
#pragma unroll
        for (int kk2 = 0; kk2 < 4; kk2++) {
            uint32_t vbh[8][2], vbl[8][2];
#pragma unroll
            for (int e = 0; e < 4; e++) {
                uint32_t off = (uint32_t)(((kk2 * 16 + vRow) * DPAD) + e * 16 + vColH) * 2;
                LDSM4T(vbh[2*e][0], vbh[2*e][1], vbh[2*e+1][0], vbh[2*e+1][1], smV + off);
                LDSM4T(vbl[2*e][0], vbl[2*e][1], vbl[2*e+1][0], vbl[2*e+1][1], smVl + off);
            }
#pragma unroll
            for (int d = 0; d < 8; d++) {
                MMA16816(o[d], pa_h[kk2], vbh[d]);
                MMA16816(o[d], pa_h[kk2], vbl[d]);
                MMA16816(o[d], pa_l[kk2], vbh[d]);
            }
        }
        __syncthreads();
    }

    // ---- epilogue: normalize and write to g_ctx ----
    const float inv0 = 1.f / lrun0;
    const float inv1 = 1.f / lrun1;
    float* c0 = g_ctx + ((size_t)(b * SEQ) + qrow0 + g) * HID + h * DK;
    float* c8 = c0 + 8 * HID;
#pragma unroll
    for (int d = 0; d < 8; d++) {
        float2 v;
        v.x = o[d][0] * inv0; v.y = o[d][1] * inv0;
        *(float2*)(c0 + d * 8 + 2 * tg) = v;
        v.x = o[d][2] * inv1; v.y = o[d][3] * inv1;
        *(float2*)(c8 + d * 8 + 2 * tg) = v;
    }
}

// ---------------------------------------------------------------------------
extern "C" void kernel_launch(void* const* d_in, const int* in_sizes, int n_in,
                              void* d_out, int out_size)
{
    (void)in_sizes; (void)n_in; (void)out_size;
    const float* tgt = (const float*)d_in[0];
    const float* Wq  = (const float*)d_in[1];
    const float* bq  = (const float*)d_in[2];
    const float* Wk  = (const float*)d_in[3];
    const float* bk  = (const float*)d_in[4];
    const float* Wv  = (const float*)d_in[5];
    const float* bv  = (const float*)d_in[6];
    const float* Wo  = (const float*)d_in[7];
    const float* bo  = (const float*)d_in[8];
    float* out = (float*)d_out;

    cudaFuncSetAttribute(gemm_mma<0>, cudaFuncAttributeMaxDynamicSharedMemorySize, GEMM_SMEM);
    cudaFuncSetAttribute(gemm_mma<1>, cudaFuncAttributeMaxDynamicSharedMemorySize, GEMM_SMEM);

    dim3 gQKV(MTOT / 128, HID / 128, 3);
    gemm_mma<0><<<gQKV, 256, GEMM_SMEM>>>(tgt, Wq, bq, Wk, bk, Wv, bv, nullptr);

    dim3 gATT(SEQ / QB, NH, BATCH);
    attn_mma<<<gATT, 256>>>();

    dim3 gOUT(MTOT / 128, HID / 128, 1);
    gemm_mma<1><<<gOUT, 256, GEMM_SMEM>>>(nullptr, Wo, bo, nullptr, nullptr, nullptr, nullptr, out);
}

// round 8
// speedup vs baseline: 2.7730x; 1.1245x over previous
#include <cuda_runtime.h>
#include <cuda_bf16.h>
#include <cstdint>

#define HID   1024
#define NH    16
#define DK    64
#define BATCH 4
#define SEQ   2048
#define MTOT  (BATCH*SEQ)

// ---- mma.sync / ldmatrix / cp.async helpers (base compute_100 features) ----
__device__ __forceinline__ uint32_t smem_to_u32(const void* p) {
    uint32_t a;
    asm("{ .reg .u64 t; cvta.to.shared.u64 t, %1; cvt.u32.u64 %0, t; }" : "=r"(a) : "l"(p));
    return a;
}
#define LDSM4(r0, r1, r2, r3, addr) \
    asm volatile("ldmatrix.sync.aligned.m8n8.x4.shared.b16 {%0,%1,%2,%3},[%4];" \
        : "=r"(r0), "=r"(r1), "=r"(r2), "=r"(r3) : "r"(addr))
#define LDSM4T(r0, r1, r2, r3, addr) \
    asm volatile("ldmatrix.sync.aligned.m8n8.x4.trans.shared.b16 {%0,%1,%2,%3},[%4];" \
        : "=r"(r0), "=r"(r1), "=r"(r2), "=r"(r3) : "r"(addr))
#define MMA16816(c, a, b) \
    asm volatile("mma.sync.aligned.m16n8k16.row.col.f32.bf16.bf16.f32 " \
        "{%0,%1,%2,%3},{%4,%5,%6,%7},{%8,%9},{%0,%1,%2,%3};" \
        : "+f"((c)[0]), "+f"((c)[1]), "+f"((c)[2]), "+f"((c)[3]) \
        : "r"((a)[0]), "r"((a)[1]), "r"((a)[2]), "r"((a)[3]), "r"((b)[0]), "r"((b)[1]))
#define CP_ASYNC16(dst, src) \
    asm volatile("cp.async.ca.shared.global [%0], [%1], 16;" :: "r"(dst), "l"(src) : "memory")
#define CP_COMMIT()  asm volatile("cp.async.commit_group;" ::: "memory")
#define CP_WAIT0()   asm volatile("cp.async.wait_group 0;" ::: "memory")

// bf16 2-term split helpers
__device__ __forceinline__ void bf16split(float x, __nv_bfloat16& h, __nv_bfloat16& l) {
    h = __float2bfloat16_rn(x);
    l = __float2bfloat16_rn(x - __bfloat162float(h));
}
__device__ __forceinline__ uint32_t pkbf(__nv_bfloat16 a, __nv_bfloat16 b) {
    __nv_bfloat162 t(a, b);
    return *(uint32_t*)&t;
}
__device__ __forceinline__ void pk2split(float x, float y, uint32_t& h, uint32_t& l) {
    __nv_bfloat16 hx, lx, hy, ly;
    bf16split(x, hx, lx); bf16split(y, hy, ly);
    h = pkbf(hx, hy); l = pkbf(lx, ly);
}

// Scratch (allocation-free rule: __device__ globals)
__device__ float g_q[(size_t)BATCH*NH*SEQ*DK];      // fp32, pre-scaled by 1/8
__device__ __nv_bfloat16 g_kh[(size_t)BATCH*NH*SEQ*DK];  // pre-split K hi plane
__device__ __nv_bfloat16 g_kl[(size_t)BATCH*NH*SEQ*DK];  // K lo plane
__device__ __nv_bfloat16 g_vh[(size_t)BATCH*NH*SEQ*DK];
__device__ __nv_bfloat16 g_vl[(size_t)BATCH*NH*SEQ*DK];
__device__ float g_ctx[(size_t)MTOT*HID];

// ---------------------------------------------------------------------------
// bf16-split tensor-core GEMM: Y = X W^T + bias
// Thread-per-row staging with STS.128 split stores.
// MODE 0, z=0: -> g_q (fp32, scaled); z=1: -> g_kh/g_kl; z=2: -> g_vh/g_vl
// MODE 1: g_ctx -> OutPlain
// ---------------------------------------------------------------------------
#define BK      32
#define NKT     (HID / BK)
#define KPAD    40
#define PLANE   (128 * KPAD)
#define STG     (4 * PLANE)
#define GEMM_SMEM (2 * STG * 2)

template<int MODE>
__global__ __launch_bounds__(256)
void gemm_mma(const float* __restrict__ Xin,
              const float* __restrict__ W0, const float* __restrict__ B0,
              const float* __restrict__ W1, const float* __restrict__ B1,
              const float* __restrict__ W2, const float* __restrict__ B2,
              float* __restrict__ OutPlain)
{
    extern __shared__ __nv_bfloat16 sm[];
    const uint32_t smb = smem_to_u32(sm);

    const float* X = (MODE == 1) ? g_ctx : Xin;
    const int z = blockIdx.z;
    const float* W;
    const float* bias;
    if (MODE == 0) {
        W    = (z == 0) ? W0 : ((z == 1) ? W1 : W2);
        bias = (z == 0) ? B0 : ((z == 1) ? B1 : B2);
    } else {
        W = W0; bias = B0;
    }

    const int m0   = blockIdx.x * 128;
    const int n0   = blockIdx.y * 128;
    const int tid  = threadIdx.x;
    const int wid  = tid >> 5;
    const int lane = tid & 31;
    const int warp_m = (wid >> 2) * 64;
    const int warp_n = (wid & 3) * 32;

    // staging: thread = one full 32-float row slice of A (tid<128) or B (tid>=128)
    const bool isB = tid >= 128;
    const int  row = tid & 127;
    const float* src0 = isB ? (W + (size_t)(n0 + row) * HID)
                            : (X + (size_t)(m0 + row) * HID);

    float4 rr[8];
    auto G2R = [&](int kt) {
        const float* s = src0 + kt * BK;
#pragma unroll
        for (int i = 0; i < 8; i++) rr[i] = *(const float4*)(s + i * 4);
    };
    auto R2S = [&](int s) {
        __nv_bfloat16* hp = sm + s * STG + (isB ? 2 : 0) * PLANE + row * KPAD;
        __nv_bfloat16* lp = hp + PLANE;
#pragma unroll
        for (int i = 0; i < 4; i++) {
            const float4 a = rr[2 * i], b = rr[2 * i + 1];
            uint4 hv, lv;
            pk2split(a.x, a.y, hv.x, lv.x);
            pk2split(a.z, a.w, hv.y, lv.y);
            pk2split(b.x, b.y, hv.z, lv.z);
            pk2split(b.z, b.w, hv.w, lv.w);
            *(uint4*)(hp + i * 8) = hv;
            *(uint4*)(lp + i * 8) = lv;
        }
    };

    float acc[4][4][4];
#pragma unroll
    for (int mt = 0; mt < 4; mt++)
#pragma unroll
        for (int nt = 0; nt < 4; nt++)
#pragma unroll
            for (int e = 0; e < 4; e++) acc[mt][nt][e] = 0.f;

    const int arow = warp_m + (lane & 15);
    const int acolL = (lane >> 4) * 8;
    const int brow = warp_n + ((lane >> 4) & 1) * 8 + (lane & 7);
    const int bcolL = ((lane >> 3) & 1) * 8;

    G2R(0); R2S(0);
    __syncthreads();

    for (int kt = 0; kt < NKT; kt++) {
        const int s = kt & 1;
        if (kt + 1 < NKT) G2R(kt + 1);

        const uint32_t sb = smb + (uint32_t)(s * STG) * 2;
        uint32_t ahi[4][4], alo[4][4], bhi[4][2], blo[4][2];
#pragma unroll
        for (int sub = 0; sub < 2; sub++) {
            const int kks = sub * 16;
#pragma unroll
            for (int mt = 0; mt < 4; mt++) {
                uint32_t ad = sb + (uint32_t)(((arow + mt * 16) * KPAD) + kks + acolL) * 2;
                LDSM4(ahi[mt][0], ahi[mt][1], ahi[mt][2], ahi[mt][3], ad);
                LDSM4(alo[mt][0], alo[mt][1], alo[mt][2], alo[mt][3], ad + PLANE * 2);
            }
#pragma unroll
            for (int p = 0; p < 2; p++) {
                uint32_t bd = sb + (uint32_t)(2 * PLANE + ((brow + p * 16) * KPAD) + kks + bcolL) * 2;
                LDSM4(bhi[2*p][0], bhi[2*p][1], bhi[2*p+1][0], bhi[2*p+1][1], bd);
                LDSM4(blo[2*p][0], blo[2*p][1], blo[2*p+1][0], blo[2*p+1][1], bd + PLANE * 2);
            }
#pragma unroll
            for (int mt = 0; mt < 4; mt++)
#pragma unroll
                for (int nt = 0; nt < 4; nt++) {
                    MMA16816(acc[mt][nt], ahi[mt], bhi[nt]);
                    MMA16816(acc[mt][nt], ahi[mt], blo[nt]);
                    MMA16816(acc[mt][nt], alo[mt], bhi[nt]);
                }
        }

        if (kt + 1 < NKT) R2S((kt + 1) & 1);
        __syncthreads();
    }

    const int g  = lane >> 2;
    const int tg = lane & 3;
#pragma unroll
    for (int mt = 0; mt < 4; mt++) {
        const int m1 = m0 + warp_m + mt * 16 + g;
        const int m2 = m1 + 8;
#pragma unroll
        for (int nt = 0; nt < 4; nt++) {
            const int n = n0 + warp_n + nt * 8 + tg * 2;
            const float bv0 = __ldg(bias + n);
            const float bv1 = __ldg(bias + n + 1);
            const float* c = acc[mt][nt];
            if (MODE == 0) {
                const int hh = n >> 6, d = n & 63;
                const size_t i1 = (((size_t)((m1 >> 11) * NH + hh)) * SEQ + (m1 & 2047)) * DK + d;
                const size_t i2 = (((size_t)((m2 >> 11) * NH + hh)) * SEQ + (m2 & 2047)) * DK + d;
                const float v0 = c[0] + bv0, v1 = c[1] + bv1;
                const float v2 = c[2] + bv0, v3 = c[3] + bv1;
                if (z == 0) {
                    *(float2*)(g_q + i1) = make_float2(v0 * 0.125f, v1 * 0.125f);
                    *(float2*)(g_q + i2) = make_float2(v2 * 0.125f, v3 * 0.125f);
                } else {
                    __nv_bfloat16* ph = (z == 1) ? g_kh : g_vh;
                    __nv_bfloat16* pl = (z == 1) ? g_kl : g_vl;
                    __nv_bfloat16 h0, l0, h1, l1;
                    bf16split(v0, h0, l0); bf16split(v1, h1, l1);
                    *(__nv_bfloat162*)(ph + i1) = __nv_bfloat162(h0, h1);
                    *(__nv_bfloat162*)(pl + i1) = __nv_bfloat162(l0, l1);
                    bf16split(v2, h0, l0); bf16split(v3, h1, l1);
                    *(__nv_bfloat162*)(ph + i2) = __nv_bfloat162(h0, h1);
                    *(__nv_bfloat162*)(pl + i2) = __nv_bfloat162(l0, l1);
                }
            } else {
                *(float2*)(OutPlain + (size_t)m1 * HID + n) = make_float2(c[0] + bv0, c[1] + bv1);
                *(float2*)(OutPlain + (size_t)m2 * HID + n) = make_float2(c[2] + bv0, c[3] + bv1);
            }
        }
    }
}

// ---------------------------------------------------------------------------
// Flash attention on tensor cores. K/V pre-split bf16 hi/lo in gmem;
// staged via double-buffered cp.async (no conversion in the loop).
// CTA: 128 queries, 8 warps (16 rows each). Key chunks of 64.
// ---------------------------------------------------------------------------
#define SC    64
#define QB    128
#define DPAD  72                   // 144B rows: conflict-free ldmatrix + 16B aligned
#define PLB   (SC * DPAD * 2)      // plane bytes = 9216
#define ATTN_SMEM (2 * 4 * PLB)    // 2 stages x 4 planes = 73728

__global__ __launch_bounds__(256)
void attn_mma()
{
    extern __shared__ __nv_bfloat16 asmem[];
    const uint32_t smBase = smem_to_u32(asmem);

    const int b    = blockIdx.z;
    const int h    = blockIdx.y;
    const int tid  = threadIdx.x;
    const int wid  = tid >> 5;
    const int lane = tid & 31;
    const int g    = lane >> 2;
    const int tg   = lane & 3;

    const size_t bh = (size_t)(b * NH + h);
    const size_t bhoff = bh * SEQ * DK;
    const int qrow0 = blockIdx.x * QB + wid * 16;

    // ---- Q a-frags (hi/lo) from fp32 gmem, loaded once ----
    uint32_t qa_h[4][4], qa_l[4][4];
    {
        const float* q0 = g_q + (bh * SEQ + qrow0 + g) * DK;
        const float* q8 = q0 + 8 * DK;
#pragma unroll
        for (int kk = 0; kk < 4; kk++) {
            float2 v;
            v = *(const float2*)(q0 + kk * 16 + 2 * tg);
            pk2split(v.x, v.y, qa_h[kk][0], qa_l[kk][0]);
            v = *(const float2*)(q8 + kk * 16 + 2 * tg);
            pk2split(v.x, v.y, qa_h[kk][1], qa_l[kk][1]);
            v = *(const float2*)(q0 + kk * 16 + 8 + 2 * tg);
            pk2split(v.x, v.y, qa_h[kk][2], qa_l[kk][2]);
            v = *(const float2*)(q8 + kk * 16 + 8 + 2 * tg);
            pk2split(v.x, v.y, qa_h[kk][3], qa_l[kk][3]);
        }
    }

    float o[8][4];
#pragma unroll
    for (int d = 0; d < 8; d++)
#pragma unroll
        for (int e = 0; e < 4; e++) o[d][e] = 0.f;
    float mrun0 = -1e30f, mrun1 = -1e30f, lrun0 = 0.f, lrun1 = 0.f;

    // cp.async prefetch of one chunk (4 planes x 64 rows x 128B payload)
    auto prefetch = [&](int kc, int s) {
        const uint32_t dstStage = smBase + (uint32_t)s * 4 * PLB;
#pragma unroll
        for (int t = 0; t < 8; t++) {
            const int plane = t >> 1;                      // compile-time after unroll
            const int inner = ((t & 1) << 8) + tid;        // 0..511
            const int r  = inner >> 3;
            const int c8 = inner & 7;
            const uint32_t dst = dstStage + (uint32_t)plane * PLB + r * (DPAD * 2) + c8 * 16;
            const __nv_bfloat16* src =
                (plane == 0 ? g_kh : plane == 1 ? g_kl : plane == 2 ? g_vh : g_vl)
                + bhoff + (size_t)(kc + r) * DK + c8 * 8;
            CP_ASYNC16(dst, src);
        }
        CP_COMMIT();
    };

    // ldmatrix address components
    const int kRow = ((lane >> 4) & 1) * 8 + (lane & 7);
    const int kColH = ((lane >> 3) & 1) * 8;
    const int vRow = ((lane >> 3) & 1) * 8 + (lane & 7);
    const int vColH = (lane >> 4) * 8;

    int s = 0;
    prefetch(0, 0);

    for (int kc = 0; kc < SEQ; kc += SC) {
        CP_WAIT0();
        __syncthreads();
        if (kc + SC < SEQ) prefetch(kc + SC, s ^ 1);

        const uint32_t stage = smBase + (uint32_t)s * 4 * PLB;
        const uint32_t smK  = stage;
        const uint32_t smKl = stage + PLB;
        const uint32_t smV  = stage + 2 * PLB;
        const uint32_t smVl = stage + 3 * PLB;

        // ---- S = Q K^T ----
        float sc[8][4];
#pragma unroll
        for (int j = 0; j < 8; j++)
#pragma unroll
            for (int e = 0; e < 4; e++) sc[j][e] = 0.f;

#pragma unroll
        for (int kk = 0; kk < 4; kk++) {
            uint32_t kbh[8][2], kbl[8][2];
#pragma unroll
            for (int p = 0; p < 4; p++) {
                uint32_t off = (uint32_t)(((p * 16 + kRow) * DPAD) + kk * 16 + kColH) * 2;
                LDSM4(kbh[2*p][0], kbh[2*p][1], kbh[2*p+1][0], kbh[2*p+1][1], smK + off);
                LDSM4(kbl[2*p][0], kbl[2*p][1], kbl[2*p+1][0], kbl[2*p+1][1], smKl + off);
            }
#pragma unroll
            for (int j = 0; j < 8; j++) {
                MMA16816(sc[j], qa_h[kk], kbh[j]);
                MMA16816(sc[j], qa_h[kk], kbl[j]);
                MMA16816(sc[j], qa_l[kk], kbh[j]);
            }
        }

        // ---- online softmax in c-frag layout ----
        float mx0 = -1e30f, mx1 = -1e30f;
#pragma unroll
        for (int j = 0; j < 8; j++) {
            mx0 = fmaxf(mx0, fmaxf(sc[j][0], sc[j][1]));
            mx1 = fmaxf(mx1, fmaxf(sc[j][2], sc[j][3]));
        }
        mx0 = fmaxf(mx0, __shfl_xor_sync(0xffffffff, mx0, 1));
        mx0 = fmaxf(mx0, __shfl_xor_sync(0xffffffff, mx0, 2));
        mx1 = fmaxf(mx1, __shfl_xor_sync(0xffffffff, mx1, 1));
        mx1 = fmaxf(mx1, __shfl_xor_sync(0xffffffff, mx1, 2));

        const float nm0 = fmaxf(mrun0, mx0);
        const float nm1 = fmaxf(mrun1, mx1);
        const float corr0 = __expf(mrun0 - nm0);
        const float corr1 = __expf(mrun1 - nm1);
        mrun0 = nm0; mrun1 = nm1;

        float sum0 = 0.f, sum1 = 0.f;
#pragma unroll
        for (int j = 0; j < 8; j++) {
            sc[j][0] = __expf(sc[j][0] - nm0); sum0 += sc[j][0];
            sc[j][1] = __expf(sc[j][1] - nm0); sum0 += sc[j][1];
            sc[j][2] = __expf(sc[j][2] - nm1); sum1 += sc[j][2];
            sc[j][3] = __expf(sc[j][3] - nm1); sum1 += sc[j][3];
        }
        sum0 += __shfl_xor_sync(0xffffffff, sum0, 1);
        sum0 += __shfl_xor_sync(0xffffffff, sum0, 2);
        sum1 += __shfl_xor_sync(0xffffffff, sum1, 1);
        sum1 += __shfl_xor_sync(0xffffffff, sum1, 2);
        lrun0 = lrun0 * corr0 + sum0;
        lrun1 = lrun1 * corr1 + sum1;

#pragma unroll
        for (int d = 0; d < 8; d++) {
            o[d][0] *= corr0; o[d][1] *= corr0;
            o[d][2] *= corr1; o[d][3] *= corr1;
        }

        // ---- pack P to bf16 hi/lo a-frags ----
        uint32_t pa_h[4][4], pa_l[4][4];
#pragma unroll
        for (int kk2 = 0; kk2 < 4; kk2++) {
            const int jL = 2 * kk2, jH = 2 * kk2 + 1;
            pk2split(sc[jL][0], sc[jL][1], pa_h[kk2][0], pa_l[kk2][0]);
            pk2split(sc[jL][2], sc[jL][3], pa_h[kk2][1], pa_l[kk2][1]);
            pk2split(sc[jH][0], sc[jH][1], pa_h[kk2][2], pa_l[kk2][2]);
            pk2split(sc[jH][2], sc[jH][3], pa_h[kk2][3], pa_l[kk2][3]);
        }

        // ---- O += P V ----
#pragma unroll
        for (int kk2 = 0; kk2 < 4; kk2++) {
            uint32_t vbh[8][2], vbl[8][2];
#pragma unroll
            for (int e = 0; e < 4; e++) {
                uint32_t off = (uint32_t)(((kk2 * 16 + vRow) * DPAD) + e * 16 + vColH) * 2;
                LDSM4T(vbh[2*e][0], vbh[2*e][1], vbh[2*e+1][0], vbh[2*e+1][1], smV + off);
                LDSM4T(vbl[2*e][0], vbl[2*e][1], vbl[2*e+1][0], vbl[2*e+1][1], smVl + off);
            }
#pragma unroll
            for (int d = 0; d < 8; d++) {
                MMA16816(o[d], pa_h[kk2], vbh[d]);
                MMA16816(o[d], pa_h[kk2], vbl[d]);
                MMA16816(o[d], pa_l[kk2], vbh[d]);
            }
        }
        s ^= 1;
    }

    // ---- epilogue ----
    const float inv0 = 1.f / lrun0;
    const float inv1 = 1.f / lrun1;
    float* c0 = g_ctx + ((size_t)(b * SEQ) + qrow0 + g) * HID + h * DK;
    float* c8 = c0 + 8 * HID;
#pragma unroll
    for (int d = 0; d < 8; d++) {
        float2 v;
        v.x = o[d][0] * inv0; v.y = o[d][1] * inv0;
        *(float2*)(c0 + d * 8 + 2 * tg) = v;
        v.x = o[d][2] * inv1; v.y = o[d][3] * inv1;
        *(float2*)(c8 + d * 8 + 2 * tg) = v;
    }
}

// ---------------------------------------------------------------------------
extern "C" void kernel_launch(void* const* d_in, const int* in_sizes, int n_in,
                              void* d_out, int out_size)
{
    (void)in_sizes; (void)n_in; (void)out_size;
    const float* tgt = (const float*)d_in[0];
    const float* Wq  = (const float*)d_in[1];
    const float* bq  = (const float*)d_in[2];
    const float* Wk  = (const float*)d_in[3];
    const float* bk  = (const float*)d_in[4];
    const float* Wv  = (const float*)d_in[5];
    const float* bv  = (const float*)d_in[6];
    const float* Wo  = (const float*)d_in[7];
    const float* bo  = (const float*)d_in[8];
    float* out = (float*)d_out;

    cudaFuncSetAttribute(gemm_mma<0>, cudaFuncAttributeMaxDynamicSharedMemorySize, GEMM_SMEM);
    cudaFuncSetAttribute(gemm_mma<1>, cudaFuncAttributeMaxDynamicSharedMemorySize, GEMM_SMEM);
    cudaFuncSetAttribute(attn_mma,    cudaFuncAttributeMaxDynamicSharedMemorySize, ATTN_SMEM);

    dim3 gQKV(MTOT / 128, HID / 128, 3);
    gemm_mma<0><<<gQKV, 256, GEMM_SMEM>>>(tgt, Wq, bq, Wk, bk, Wv, bv, nullptr);

    dim3 gATT(SEQ / QB, NH, BATCH);
    attn_mma<<<gATT, 256, ATTN_SMEM>>>();

    dim3 gOUT(MTOT / 128, HID / 128, 1);
    gemm_mma<1><<<gOUT, 256, GEMM_SMEM>>>(nullptr, Wo, bo, nullptr, nullptr, nullptr, nullptr, out);
}